// round 11
// baseline (speedup 1.0000x reference)
#include <cuda_runtime.h>
#include <cuda_fp16.h>
#include <math.h>
#include <stdint.h>

#define NN 512
#define HH 512
#define XD 128
#define NJT 16
#define NIT 128

#define HXS 520            /* padded row stride (floats) for pre-pass hx/hyb */
#define A_STR 1040         /* A-tile row stride bytes (65*16 -> ldsm conflict-free) */

// smem layout (total 208000 B, 1 CTA/SM, 512 threads)
#define OFF_A     0         /* fp16 A tile: 128 x 1040 = 133120            */
#define OFF_HXPP  133120    /* pre-pass hx: 32 x 2080 = 66560              */
#define OFF_HYPP  199680    /* pre-pass hyb: 4 x 2080 = 8320 -> end 208000 */
// mainloop aliases (valid after A-tile is built):
#define OFF_B     133120    /* 3 stages x 10240 = 30720                    */
#define OFF_B2    163840
#define OFF_W3    165888
#define OFF_ROW   167936    /* 128*2*4 = 1024                              */
#define OFF_E     168960    /* 128*4                                       */
#define SMEM_MAIN 208000
#define BSTG 10240

// ---------------- device scratch ----------------
__device__ float  g_hx [NN*HH];
__device__ float  g_hyb[NN*HH];
__device__ __half g_w2t[HH*HH];    // W2^T fp16, [c*512 + k]
__device__ float  g_partial[NN*NJT];
__device__ float  g_t0[NN];

// ---------------- helpers ----------------
__device__ __forceinline__ uint32_t smem_u32(const void* p) {
    uint32_t a;
    asm("{ .reg .u64 t; cvta.to.shared.u64 t, %1; cvt.u32.u64 %0, t; }" : "=r"(a) : "l"(p));
    return a;
}
__device__ __forceinline__ void ldsm4(uint32_t* r, uint32_t addr) {
    asm volatile("ldmatrix.sync.aligned.m8n8.x4.shared.b16 {%0,%1,%2,%3}, [%4];"
        : "=r"(r[0]), "=r"(r[1]), "=r"(r[2]), "=r"(r[3]) : "r"(addr));
}
__device__ __forceinline__ void mma16816(float* d, const uint32_t* a, uint32_t b0, uint32_t b1) {
    asm volatile("mma.sync.aligned.m16n8k16.row.col.f32.f16.f16.f32 "
        "{%0,%1,%2,%3}, {%4,%5,%6,%7}, {%8,%9}, {%0,%1,%2,%3};"
        : "+f"(d[0]), "+f"(d[1]), "+f"(d[2]), "+f"(d[3])
        : "r"(a[0]), "r"(a[1]), "r"(a[2]), "r"(a[3]), "r"(b0), "r"(b1));
}
__device__ __forceinline__ void cp16(uint32_t dst, const void* src) {
    asm volatile("cp.async.cg.shared.global [%0], [%1], 16;" :: "r"(dst), "l"(src));
}
#define CP_COMMIT() asm volatile("cp.async.commit_group;" ::: "memory")
#define CP_WAIT1()  asm volatile("cp.async.wait_group 1;" ::: "memory")
#define CP_WAIT0()  asm volatile("cp.async.wait_group 0;" ::: "memory")

__device__ __forceinline__ uint32_t pack2(float v0, float v1) {
    __half2 h = __floats2half2_rn(v0, v1);
    return *(uint32_t*)&h;
}

// ---------------------------------------------------------------------------
// Prologue: z=0: hx = x @ W1x ; z=1: hyb = y @ W1y + b1 ; z=2: W2^T -> fp16
// ---------------------------------------------------------------------------
__global__ void __launch_bounds__(256) prologue_gemm(
    const float* __restrict__ x, const float* __restrict__ y,
    const float* __restrict__ w1x, const float* __restrict__ w1y,
    const float* __restrict__ b1, const float* __restrict__ w2)
{
    int tid = threadIdx.x;

    if (blockIdx.z == 2) {
        int k0 = blockIdx.y * 64, c0 = blockIdx.x * 64;
        #pragma unroll
        for (int s = 0; s < 16; s++) {
            int idx = tid + s * 256;
            int cc = idx >> 6, kk = idx & 63;
            g_w2t[(c0 + cc) * HH + k0 + kk] =
                __float2half_rn(w2[(k0 + kk) * HH + c0 + cc]);
        }
        return;
    }

    const float* A = (blockIdx.z == 0) ? x   : y;
    const float* B = (blockIdx.z == 0) ? w1x : w1y;
    float*       C = (blockIdx.z == 0) ? g_hx : g_hyb;

    int m0 = blockIdx.y * 64, n0 = blockIdx.x * 64;
    __shared__ float sA[16][64 + 2];
    __shared__ float sB[16][64 + 2];
    int ty = tid >> 4, tx = tid & 15;

    float acc[4][4] = {};
    for (int k0 = 0; k0 < XD; k0 += 16) {
        #pragma unroll
        for (int s = 0; s < 4; s++) {
            int idx = tid + s * 256;
            int kk = idx & 15, m = idx >> 4;
            sA[kk][m] = A[(m0 + m) * XD + k0 + kk];
        }
        #pragma unroll
        for (int s = 0; s < 4; s++) {
            int idx = tid + s * 256;
            int nn = idx & 63, kk = idx >> 6;
            sB[kk][nn] = B[(k0 + kk) * HH + n0 + nn];
        }
        __syncthreads();
        #pragma unroll
        for (int kk = 0; kk < 16; kk++) {
            float a[4], b[4];
            #pragma unroll
            for (int u = 0; u < 4; u++) a[u] = sA[kk][ty * 4 + u];
            #pragma unroll
            for (int v = 0; v < 4; v++) b[v] = sB[kk][tx * 4 + v];
            #pragma unroll
            for (int u = 0; u < 4; u++)
                #pragma unroll
                for (int v = 0; v < 4; v++)
                    acc[u][v] = fmaf(a[u], b[v], acc[u][v]);
        }
        __syncthreads();
    }
    #pragma unroll
    for (int u = 0; u < 4; u++)
        #pragma unroll
        for (int v = 0; v < 4; v++) {
            int m = m0 + ty * 4 + u, n = n0 + tx * 4 + v;
            float val = acc[u][v];
            if (blockIdx.z == 1) val += b1[n];
            C[m * HH + n] = val;
        }
}

// ---------------------------------------------------------------------------
// Main HMMA kernel. grid (16,128), 512 threads (16 warps, 8 m x 2 n).
// Pre-pass builds the full 128x512 fp16 A tile in SMEM once; mainloop is
// pure ldsm + MMA over a 3-stage B ring (prefetch dist 2, one sync/step).
// ---------------------------------------------------------------------------
__global__ void __launch_bounds__(512, 1) main_mma(
    const float* __restrict__ b2, const float* __restrict__ w3,
    const float* __restrict__ b3)
{
    extern __shared__ char smem[];
    uint32_t sb = smem_u32(smem);
    int tid = threadIdx.x, lane = tid & 31, wid = tid >> 5;
    int warp_m = wid >> 1, warp_n = wid & 1;    // 8 row-groups x 2 col-halves
    int jt = blockIdx.x, it = blockIdx.y;

    float* b2s   = (float*)(smem + OFF_B2);
    float* w3s   = (float*)(smem + OFF_W3);
    float* sRow  = (float*)(smem + OFF_ROW);
    float* sE    = (float*)(smem + OFF_E);

    // ---- pre-pass: stage hx (32 rows) + hyb (4 rows) fp32 ----
    #pragma unroll
    for (int u = 0; u < 8; u++) {
        int idx = tid + u * 512;                 // 4096 chunks of 16B
        int row = idx >> 7, q = idx & 127;
        cp16(sb + OFF_HXPP + (uint32_t)(row * (HXS*4) + q * 16),
             g_hx + (jt * 32 + row) * HH + q * 4);
    }
    {
        int row = tid >> 7, q = tid & 127;       // 512 chunks
        cp16(sb + OFF_HYPP + (uint32_t)(row * (HXS*4) + q * 16),
             g_hyb + (it * 4 + row) * HH + q * 4);
    }
    CP_COMMIT();
    CP_WAIT0();
    __syncthreads();

    // ---- build fp16 A tile: A[r][k] = relu(hx[r&31][k] + hyb[r>>5][k]) ----
    {
        int row = tid >> 2;                      // 0..127
        int kq  = (tid & 3) * 128;               // 128 k per thread
        const float* hxr = (const float*)(smem + OFF_HXPP) + (row & 31) * HXS + kq;
        const float* hyr = (const float*)(smem + OFF_HYPP) + (row >> 5) * HXS + kq;
        uint4* arow = (uint4*)(smem + row * A_STR + kq * 2);
        #pragma unroll
        for (int t = 0; t < 16; t++) {           // 8 k per iter
            float4 a0 = *(const float4*)(hxr + t * 8);
            float4 a1 = *(const float4*)(hxr + t * 8 + 4);
            float4 c0 = *(const float4*)(hyr + t * 8);
            float4 c1 = *(const float4*)(hyr + t * 8 + 4);
            uint4 o;
            o.x = pack2(fmaxf(a0.x + c0.x, 0.f), fmaxf(a0.y + c0.y, 0.f));
            o.y = pack2(fmaxf(a0.z + c0.z, 0.f), fmaxf(a0.w + c0.w, 0.f));
            o.z = pack2(fmaxf(a1.x + c1.x, 0.f), fmaxf(a1.y + c1.y, 0.f));
            o.w = pack2(fmaxf(a1.z + c1.z, 0.f), fmaxf(a1.w + c1.w, 0.f));
            arow[t] = o;
        }
    }
    __syncthreads();   // A done; hx/hyb region now free for B ring alias

    // ---- B stages 0 and 1 ----
    {
        int col = tid >> 2, q = tid & 3;         // 512 chunks per stage
        cp16(sb + OFF_B + (uint32_t)(col * 80 + q * 16),
             g_w2t + col * HH + q * 8);
        CP_COMMIT();
        cp16(sb + OFF_B + BSTG + (uint32_t)(col * 80 + q * 16),
             g_w2t + col * HH + 32 + q * 8);
        CP_COMMIT();
    }
    if (tid < HH) { b2s[tid] = b2[tid]; w3s[tid] = w3[tid]; }

    const int g = lane >> 2;

    // A fragment address: row = warp_m*16 + ((lane>>3)&1)*8 + (lane&7)
    const uint32_t a_base = sb +
        (uint32_t)((warp_m * 16 + ((lane >> 3) & 1) * 8 + (lane & 7)) * A_STR)
        + (uint32_t)((lane >> 4) * 16);          // chunk parity
    const uint32_t bcol = (uint32_t)(warp_n * 64 + (lane & 7) + ((lane >> 4) & 1) * 8);
    const uint32_t bchk_base = (uint32_t)((lane >> 3) & 1);

    float ptl[2] = {0.f, 0.f};
    float acc[8][4];

    CP_WAIT1();          // stage 0 ready
    __syncthreads();

    for (int s = 0; s < 64; s++) {
        int nb = s >> 4, kc = s & 15;

        if (s) {
            if (s < 63) { CP_WAIT1(); } else { CP_WAIT0(); }
            __syncthreads();
        }

        // prefetch B for step s+2 into ring slot (s+2)%3
        if (s < 62) {
            int s2 = s + 2;
            int nb2 = s2 >> 4, kc2 = s2 & 15;
            uint32_t stg = sb + OFF_B + (uint32_t)((s2 % 3) * BSTG);
            int col = tid >> 2, q = tid & 3;
            cp16(stg + (uint32_t)(col * 80 + q * 16),
                 g_w2t + (nb2 * 128 + col) * HH + kc2 * 32 + q * 8);
            CP_COMMIT();
        }

        if (kc == 0) {
            #pragma unroll
            for (int tn = 0; tn < 8; tn++)
                #pragma unroll
                for (int v = 0; v < 4; v++) acc[tn][v] = 0.f;
        }

        uint32_t stage = sb + OFF_B + (uint32_t)((s % 3) * BSTG);

        #pragma unroll
        for (int ks = 0; ks < 2; ks++) {
            uint32_t ah[4];
            ldsm4(ah, a_base + (uint32_t)((kc * 4 + ks * 2) * 16));
            uint32_t bchk = (uint32_t)(ks * 2) + bchk_base;
            #pragma unroll
            for (int p = 0; p < 4; p++) {
                uint32_t addr = stage + (bcol + p * 16) * 80 + bchk * 16;
                uint32_t bh[4];
                ldsm4(bh, addr);
                mma16816(acc[2*p],   ah, bh[0], bh[1]);
                mma16816(acc[2*p+1], ah, bh[2], bh[3]);
            }
        }

        // ---- end of nb block: fold into per-row scalars ----
        if (kc == 15) {
            #pragma unroll
            for (int tn = 0; tn < 8; tn++) {
                int c0 = nb * 128 + warp_n * 64 + tn * 8 + (lane & 3) * 2;
                float w3a = w3s[c0], w3b = w3s[c0 + 1];
                float b2a = b2s[c0], b2b = b2s[c0 + 1];
                float v0 = acc[tn][0] + b2a;
                float v1 = acc[tn][1] + b2b;
                float v2 = acc[tn][2] + b2a;
                float v3 = acc[tn][3] + b2b;
                ptl[0] = fmaf(fmaxf(v0, 0.f), w3a, fmaf(fmaxf(v1, 0.f), w3b, ptl[0]));
                ptl[1] = fmaf(fmaxf(v2, 0.f), w3a, fmaf(fmaxf(v3, 0.f), w3b, ptl[1]));
            }
        }
    }

    // ---- reduce across the 4 column-thread groups (same rows) ----
    #pragma unroll
    for (int u = 0; u < 2; u++) {
        ptl[u] += __shfl_xor_sync(0xffffffffu, ptl[u], 1);
        ptl[u] += __shfl_xor_sync(0xffffffffu, ptl[u], 2);
    }
    __syncthreads();
    if ((lane & 3) == 0) {
        sRow[(warp_m * 16 + g) * 2 + warp_n]     = ptl[0];
        sRow[(warp_m * 16 + 8 + g) * 2 + warp_n] = ptl[1];
    }
    __syncthreads();

    if (tid < 128) {
        float ssum = sRow[tid * 2] + sRow[tid * 2 + 1] + b3[0];
        float T1 = (ssum > 20.f) ? ssum : log1pf(expf(ssum));
        int ii = it * 4 + (tid >> 5);
        int jj = jt * 32 + (tid & 31);
        if (ii == jj) g_t0[ii] = T1;
        sE[tid] = expf(T1);
    }
    __syncthreads();

    if (tid < 4) {
        float ssum = 0.f;
        #pragma unroll
        for (int jl = 0; jl < 32; jl++) ssum += sE[tid * 32 + jl];
        g_partial[(it * 4 + tid) * NJT + jt] = ssum;
    }
}

// ---------------------------------------------------------------------------
// Finalize
// ---------------------------------------------------------------------------
__global__ void finalize_kernel(float* __restrict__ out)
{
    int tid = threadIdx.x;
    float s = 0.f;
    #pragma unroll
    for (int jt = 0; jt < NJT; jt++) s += g_partial[tid * NJT + jt];
    float val = g_t0[tid] - logf(s);

    __shared__ float sh[512];
    sh[tid] = val;
    __syncthreads();
    for (int off = 256; off > 0; off >>= 1) {
        if (tid < off) sh[tid] += sh[tid + off];
        __syncthreads();
    }
    if (tid == 0) out[0] = sh[0] / 512.f + logf(512.f);
}

extern "C" void kernel_launch(void* const* d_in, const int* in_sizes, int n_in,
                              void* d_out, int out_size)
{
    const float* x   = (const float*)d_in[0];
    const float* y   = (const float*)d_in[1];
    const float* w1x = (const float*)d_in[2];
    const float* w1y = (const float*)d_in[3];
    const float* b1  = (const float*)d_in[4];
    const float* w2  = (const float*)d_in[5];
    const float* b2  = (const float*)d_in[6];
    const float* w3  = (const float*)d_in[7];
    const float* b3  = (const float*)d_in[8];
    float* out = (float*)d_out;

    cudaFuncSetAttribute(main_mma, cudaFuncAttributeMaxDynamicSharedMemorySize, SMEM_MAIN);

    dim3 g1(8, 8, 3);
    prologue_gemm<<<g1, 256>>>(x, y, w1x, w1y, b1, w2);
    dim3 g2(NJT, NIT);
    main_mma<<<g2, 512, SMEM_MAIN>>>(b2, w3, b3);
    finalize_kernel<<<1, 512>>>(out);
}

// round 12
// speedup vs baseline: 1.5898x; 1.5898x over previous
#include <cuda_runtime.h>
#include <cuda_fp16.h>
#include <math.h>
#include <stdint.h>

#define NN 512
#define HH 512
#define XD 128
#define NJT 16
#define NIT 128

#define HXS 520            /* padded row stride (floats) for hx/hyb smem */

// smem byte offsets (per CTA total 111232 B -> 2 CTAs/SM)
#define OFF_HX   0          /* 32 rows x 520 x 4 = 66560 */
#define OFF_HYB  66560      /* 4 rows x 520 x 4 = 8320   */
#define OFF_B    74880      /* 3 stages x 10240          */
#define OFF_B2   105600
#define OFF_W3   107648
#define OFF_ROW  109696
#define OFF_E    110720
#define SMEM_MAIN 111232
#define BSTG 10240

// ---------------- device scratch ----------------
__device__ float  g_hx [NN*HH];
__device__ float  g_hyb[NN*HH];
__device__ __half g_w2t[HH*HH];    // W2^T fp16, [c*512 + k]
__device__ float  g_partial[NN*NJT];
__device__ float  g_t0[NN];
__device__ unsigned int g_count = 0;

// ---------------- helpers ----------------
__device__ __forceinline__ uint32_t smem_u32(const void* p) {
    uint32_t a;
    asm("{ .reg .u64 t; cvta.to.shared.u64 t, %1; cvt.u32.u64 %0, t; }" : "=r"(a) : "l"(p));
    return a;
}
__device__ __forceinline__ void ldsm4(uint32_t* r, uint32_t addr) {
    asm volatile("ldmatrix.sync.aligned.m8n8.x4.shared.b16 {%0,%1,%2,%3}, [%4];"
        : "=r"(r[0]), "=r"(r[1]), "=r"(r[2]), "=r"(r[3]) : "r"(addr));
}
__device__ __forceinline__ void mma16816(float* d, const uint32_t* a, uint32_t b0, uint32_t b1) {
    asm volatile("mma.sync.aligned.m16n8k16.row.col.f32.f16.f16.f32 "
        "{%0,%1,%2,%3}, {%4,%5,%6,%7}, {%8,%9}, {%0,%1,%2,%3};"
        : "+f"(d[0]), "+f"(d[1]), "+f"(d[2]), "+f"(d[3])
        : "r"(a[0]), "r"(a[1]), "r"(a[2]), "r"(a[3]), "r"(b0), "r"(b1));
}
__device__ __forceinline__ void cp16(uint32_t dst, const void* src) {
    asm volatile("cp.async.cg.shared.global [%0], [%1], 16;" :: "r"(dst), "l"(src));
}
#define CP_COMMIT() asm volatile("cp.async.commit_group;" ::: "memory")
#define CP_WAIT1()  asm volatile("cp.async.wait_group 1;" ::: "memory")
#define CP_WAIT0()  asm volatile("cp.async.wait_group 0;" ::: "memory")

__device__ __forceinline__ uint32_t pack2(float v0, float v1) {
    __half2 h = __floats2half2_rn(v0, v1);
    return *(uint32_t*)&h;
}

// ---------------------------------------------------------------------------
// Prologue: z=0: hx = x @ W1x ; z=1: hyb = y @ W1y + b1 ; z=2: W2^T -> fp16
// ---------------------------------------------------------------------------
__global__ void __launch_bounds__(256) prologue_gemm(
    const float* __restrict__ x, const float* __restrict__ y,
    const float* __restrict__ w1x, const float* __restrict__ w1y,
    const float* __restrict__ b1, const float* __restrict__ w2)
{
    int tid = threadIdx.x;

    if (blockIdx.z == 2) {
        int k0 = blockIdx.y * 64, c0 = blockIdx.x * 64;
        #pragma unroll
        for (int s = 0; s < 16; s++) {
            int idx = tid + s * 256;
            int cc = idx >> 6, kk = idx & 63;
            g_w2t[(c0 + cc) * HH + k0 + kk] =
                __float2half_rn(w2[(k0 + kk) * HH + c0 + cc]);
        }
        return;
    }

    const float* A = (blockIdx.z == 0) ? x   : y;
    const float* B = (blockIdx.z == 0) ? w1x : w1y;
    float*       C = (blockIdx.z == 0) ? g_hx : g_hyb;

    int m0 = blockIdx.y * 64, n0 = blockIdx.x * 64;
    __shared__ float sA[16][64 + 2];
    __shared__ float sB[16][64 + 2];
    int ty = tid >> 4, tx = tid & 15;

    float acc[4][4] = {};
    for (int k0 = 0; k0 < XD; k0 += 16) {
        #pragma unroll
        for (int s = 0; s < 4; s++) {
            int idx = tid + s * 256;
            int kk = idx & 15, m = idx >> 4;
            sA[kk][m] = A[(m0 + m) * XD + k0 + kk];
        }
        #pragma unroll
        for (int s = 0; s < 4; s++) {
            int idx = tid + s * 256;
            int nn = idx & 63, kk = idx >> 6;
            sB[kk][nn] = B[(k0 + kk) * HH + n0 + nn];
        }
        __syncthreads();
        #pragma unroll
        for (int kk = 0; kk < 16; kk++) {
            float a[4], b[4];
            #pragma unroll
            for (int u = 0; u < 4; u++) a[u] = sA[kk][ty * 4 + u];
            #pragma unroll
            for (int v = 0; v < 4; v++) b[v] = sB[kk][tx * 4 + v];
            #pragma unroll
            for (int u = 0; u < 4; u++)
                #pragma unroll
                for (int v = 0; v < 4; v++)
                    acc[u][v] = fmaf(a[u], b[v], acc[u][v]);
        }
        __syncthreads();
    }
    #pragma unroll
    for (int u = 0; u < 4; u++)
        #pragma unroll
        for (int v = 0; v < 4; v++) {
            int m = m0 + ty * 4 + u, n = n0 + tx * 4 + v;
            float val = acc[u][v];
            if (blockIdx.z == 1) val += b1[n];
            C[m * HH + n] = val;
        }
}

// ---------------------------------------------------------------------------
// Main HMMA kernel (R8 schedule), fp16 in / fp32 acc. grid (16, 128),
// 256 thr, 8 warps (4 m x 2 n), 2 CTAs/SM. 3-stage B ring (prefetch dist 2,
// one sync/step), pipelined A-build. Last CTA performs the final reduction.
// ---------------------------------------------------------------------------
__global__ void __launch_bounds__(256, 2) main_mma(
    const float* __restrict__ b2, const float* __restrict__ w3,
    const float* __restrict__ b3, float* __restrict__ out)
{
    extern __shared__ char smem[];
    uint32_t sb = smem_u32(smem);
    int tid = threadIdx.x, lane = tid & 31, wid = tid >> 5;
    int warp_m = wid >> 1, warp_n = wid & 1;
    int jt = blockIdx.x, it = blockIdx.y;

    float* hx_s  = (float*)(smem + OFF_HX);
    float* hyb_s = (float*)(smem + OFF_HYB);
    float* b2s   = (float*)(smem + OFF_B2);
    float* w3s   = (float*)(smem + OFF_W3);
    float* sRow  = (float*)(smem + OFF_ROW);
    float* sE    = (float*)(smem + OFF_E);

    // ---- group 0: hx (32 rows) + hyb (4 rows) + B stage 0 ----
    #pragma unroll
    for (int u = 0; u < 16; u++) {
        int idx = tid + u * 256;
        int row = idx >> 7, q = idx & 127;
        cp16(sb + OFF_HX + (uint32_t)(row * (HXS*4) + q * 16),
             g_hx + (jt * 32 + row) * HH + q * 4);
    }
    #pragma unroll
    for (int u = 0; u < 2; u++) {
        int idx = tid + u * 256;
        int row = idx >> 7, q = idx & 127;
        cp16(sb + OFF_HYB + (uint32_t)(row * (HXS*4) + q * 16),
             g_hyb + (it * 4 + row) * HH + q * 4);
    }
    #pragma unroll
    for (int u = 0; u < 2; u++) {            // B step 0 (nb=0,kc=0)
        int idx = tid + u * 256;
        int col = idx >> 2, q = idx & 3;
        cp16(sb + OFF_B + (uint32_t)(col * 80 + q * 16),
             g_w2t + col * HH + q * 8);
    }
    CP_COMMIT();
    // ---- group 1: B stage 1 (step 1: nb=0, kc=1) ----
    #pragma unroll
    for (int u = 0; u < 2; u++) {
        int idx = tid + u * 256;
        int col = idx >> 2, q = idx & 3;
        cp16(sb + OFF_B + BSTG + (uint32_t)(col * 80 + q * 16),
             g_w2t + col * HH + 32 + q * 8);
    }
    CP_COMMIT();

    for (int c = tid; c < HH; c += 256) { b2s[c] = b2[c]; w3s[c] = w3[c]; }

    const int g  = lane >> 2;          // 0..7
    const int qk = (lane & 3) * 2;     // 0,2,4,6
    const float* hyr = hyb_s + warp_m * HXS;

    float ptl[4] = {0.f, 0.f, 0.f, 0.f};
    float acc[2][8][4];
    uint32_t ah_cur[2][4], ah_nxt[2][4];

    const uint32_t bcol = (uint32_t)(warp_n * 64 + (lane & 7) + ((lane >> 4) & 1) * 8);
    const uint32_t bchk_base = (uint32_t)((lane >> 3) & 1);

    #define BUILD_A(dst, kb_) do {                                              \
        int kb = (kb_);                                                         \
        _Pragma("unroll")                                                       \
        for (int tm = 0; tm < 2; tm++) {                                        \
            int r0 = (warp_m * 32 + tm * 16 + g) & 31;                          \
            int r1 = (warp_m * 32 + tm * 16 + 8 + g) & 31;                      \
            float2 x00 = *(const float2*)(hx_s + r0 * HXS + kb + qk);           \
            float2 x01 = *(const float2*)(hx_s + r0 * HXS + kb + qk + 8);       \
            float2 x10 = *(const float2*)(hx_s + r1 * HXS + kb + qk);           \
            float2 x11 = *(const float2*)(hx_s + r1 * HXS + kb + qk + 8);       \
            float2 y0  = *(const float2*)(hyr + kb + qk);                       \
            float2 y1  = *(const float2*)(hyr + kb + qk + 8);                   \
            dst[tm][0] = pack2(fmaxf(x00.x + y0.x, 0.f), fmaxf(x00.y + y0.y, 0.f)); \
            dst[tm][1] = pack2(fmaxf(x10.x + y0.x, 0.f), fmaxf(x10.y + y0.y, 0.f)); \
            dst[tm][2] = pack2(fmaxf(x01.x + y1.x, 0.f), fmaxf(x01.y + y1.y, 0.f)); \
            dst[tm][3] = pack2(fmaxf(x11.x + y1.x, 0.f), fmaxf(x11.y + y1.y, 0.f)); \
        }                                                                       \
    } while (0)

    #define MMA_BLOCK(ah, stage, ks) do {                                       \
        uint32_t bchk = (uint32_t)((ks) * 2) + bchk_base;                       \
        _Pragma("unroll")                                                       \
        for (int p = 0; p < 4; p++) {                                           \
            uint32_t addr = (stage) + (bcol + p * 16) * 80 + bchk * 16;         \
            uint32_t bh[4];                                                     \
            ldsm4(bh, addr);                                                    \
            _Pragma("unroll")                                                   \
            for (int tm = 0; tm < 2; tm++) {                                    \
                mma16816(acc[tm][2*p],   ah[tm], bh[0], bh[1]);                 \
                mma16816(acc[tm][2*p+1], ah[tm], bh[2], bh[3]);                 \
            }                                                                   \
        }                                                                       \
    } while (0)

    // wait for group 0 (hx/hyb/stage0); group 1 may stay in flight
    CP_WAIT1();
    __syncthreads();

    BUILD_A(ah_cur, 0);   // (s=0, ks=0)

    for (int s = 0; s < 64; s++) {
        int nb = s >> 4, kc = s & 15;
        (void)nb;

        if (s) {
            if (s < 63) { CP_WAIT1(); } else { CP_WAIT0(); }
            __syncthreads();
        }

        // prefetch B for step s+2 into ring slot (s+2)%3 (read last at s-1)
        if (s < 62) {
            int s2 = s + 2;
            int nb2 = s2 >> 4, kc2 = s2 & 15;
            uint32_t stg = sb + OFF_B + (uint32_t)((s2 % 3) * BSTG);
            #pragma unroll
            for (int u = 0; u < 2; u++) {
                int idx = tid + u * 256;
                int col = idx >> 2, q = idx & 3;
                cp16(stg + (uint32_t)(col * 80 + q * 16),
                     g_w2t + (nb2 * 128 + col) * HH + kc2 * 32 + q * 8);
            }
            CP_COMMIT();
        }

        if (kc == 0) {
            #pragma unroll
            for (int tm = 0; tm < 2; tm++)
                #pragma unroll
                for (int tn = 0; tn < 8; tn++)
                    #pragma unroll
                    for (int v = 0; v < 4; v++) acc[tm][tn][v] = 0.f;
        }

        uint32_t stage = sb + OFF_B + (uint32_t)((s % 3) * BSTG);

        // ks=0: MMA with ah_cur; build ah_nxt (this step, ks=1) under the MMAs
        BUILD_A(ah_nxt, kc * 32 + 16);
        MMA_BLOCK(ah_cur, stage, 0);
        // ks=1: MMA with ah_nxt; build ah_cur for (s+1, ks=0) under the MMAs
        BUILD_A(ah_cur, ((s + 1) & 15) * 32);
        MMA_BLOCK(ah_nxt, stage, 1);

        // ---- end of nb block: fold into per-row scalars ----
        if (kc == 15) {
            #pragma unroll
            for (int tm = 0; tm < 2; tm++)
                #pragma unroll
                for (int tn = 0; tn < 8; tn++) {
                    int c0 = nb * 128 + warp_n * 64 + tn * 8 + (lane & 3) * 2;
                    float w3a = w3s[c0], w3b = w3s[c0 + 1];
                    float b2a = b2s[c0], b2b = b2s[c0 + 1];
                    float v0 = acc[tm][tn][0] + b2a;
                    float v1 = acc[tm][tn][1] + b2b;
                    float v2 = acc[tm][tn][2] + b2a;
                    float v3 = acc[tm][tn][3] + b2b;
                    ptl[tm*2+0] = fmaf(fmaxf(v0, 0.f), w3a, fmaf(fmaxf(v1, 0.f), w3b, ptl[tm*2+0]));
                    ptl[tm*2+1] = fmaf(fmaxf(v2, 0.f), w3a, fmaf(fmaxf(v3, 0.f), w3b, ptl[tm*2+1]));
                }
        }
    }

    // ---- reduce across the 4 column-thread groups (same rows) ----
    #pragma unroll
    for (int u = 0; u < 4; u++) {
        ptl[u] += __shfl_xor_sync(0xffffffffu, ptl[u], 1);
        ptl[u] += __shfl_xor_sync(0xffffffffu, ptl[u], 2);
    }
    __syncthreads();
    if ((lane & 3) == 0) {
        int q = lane >> 2;
        sRow[(warp_m * 32 +  0 + q) * 2 + warp_n] = ptl[0];
        sRow[(warp_m * 32 +  8 + q) * 2 + warp_n] = ptl[1];
        sRow[(warp_m * 32 + 16 + q) * 2 + warp_n] = ptl[2];
        sRow[(warp_m * 32 + 24 + q) * 2 + warp_n] = ptl[3];
    }
    __syncthreads();

    if (tid < 128) {
        float ssum = sRow[tid * 2] + sRow[tid * 2 + 1] + b3[0];
        float T1 = (ssum > 20.f) ? ssum : log1pf(expf(ssum));
        int ii = it * 4 + (tid >> 5);
        int jj = jt * 32 + (tid & 31);
        if (ii == jj) g_t0[ii] = T1;
        sE[tid] = expf(T1);
    }
    __syncthreads();

    if (tid < 4) {
        float ssum = 0.f;
        #pragma unroll
        for (int jl = 0; jl < 32; jl++) ssum += sE[tid * 32 + jl];
        g_partial[(it * 4 + tid) * NJT + jt] = ssum;
    }

    // ---- fused finalize: last CTA reduces everything ----
    __threadfence();
    __shared__ int is_last;
    __syncthreads();                 // g_partial/g_t0 writes done, sRow reuse safe
    if (tid == 0) {
        unsigned int old = atomicAdd(&g_count, 1u);
        is_last = (old == (unsigned int)(NJT * NIT - 1));
    }
    __syncthreads();
    if (is_last) {
        __threadfence();
        float v = 0.f;
        #pragma unroll
        for (int u = 0; u < 2; u++) {
            int i = tid + u * 256;
            float ssum2 = 0.f;
            #pragma unroll
            for (int j2 = 0; j2 < NJT; j2++) ssum2 += g_partial[i * NJT + j2];
            v += g_t0[i] - logf(ssum2);
        }
        #pragma unroll
        for (int o = 16; o; o >>= 1) v += __shfl_xor_sync(0xffffffffu, v, o);
        if (lane == 0) sRow[wid] = v;
        __syncthreads();
        if (tid == 0) {
            float t = 0.f;
            #pragma unroll
            for (int w = 0; w < 8; w++) t += sRow[w];
            out[0] = t / 512.f + logf(512.f);
            g_count = 0;             // reset for next graph replay
        }
    }
}

extern "C" void kernel_launch(void* const* d_in, const int* in_sizes, int n_in,
                              void* d_out, int out_size)
{
    const float* x   = (const float*)d_in[0];
    const float* y   = (const float*)d_in[1];
    const float* w1x = (const float*)d_in[2];
    const float* w1y = (const float*)d_in[3];
    const float* b1  = (const float*)d_in[4];
    const float* w2  = (const float*)d_in[5];
    const float* b2  = (const float*)d_in[6];
    const float* w3  = (const float*)d_in[7];
    const float* b3  = (const float*)d_in[8];
    float* out = (float*)d_out;

    cudaFuncSetAttribute(main_mma, cudaFuncAttributeMaxDynamicSharedMemorySize, SMEM_MAIN);

    dim3 g1(8, 8, 3);
    prologue_gemm<<<g1, 256>>>(x, y, w1x, w1y, b1, w2);
    dim3 g2(NJT, NIT);
    main_mma<<<g2, 256, SMEM_MAIN>>>(b2, w3, b3, out);
}

// round 15
// speedup vs baseline: 1.6399x; 1.0315x over previous
#include <cuda_runtime.h>
#include <cuda_fp16.h>
#include <math.h>
#include <stdint.h>

#define NN 512
#define HH 512
#define XD 128
#define NJT 16
#define NIT 128

#define HXS 520            /* padded row stride (floats) for hx/hyb smem */

// smem byte offsets (per CTA total 111232 B -> 2 CTAs/SM)
#define OFF_ARING 0         /* phase2: 3 x 8192 A-frag ring (aliases hx)  */
#define OFF_HX   0          /* phase1: 32 rows x 520 x 4 = 66560          */
#define OFF_HYB  66560      /* 4 rows x 520 x 4 = 8320                    */
#define OFF_B    74880      /* 3 stages x 10240                           */
#define OFF_B2   105600
#define OFF_W3   107648
#define OFF_ROW  109696
#define OFF_E    110720
#define SMEM_MAIN 111232
#define BSTG 10240

// ---------------- device scratch ----------------
__device__ float  g_hx [NN*HH];
__device__ float  g_hyb[NN*HH];
__device__ __half g_w2t[HH*HH];    // W2^T fp16, [c*512 + k]
__device__ float  g_partial[NN*NJT];
__device__ float  g_t0[NN];
// A fragments: per CTA 8192 uint4 (16 kc x 512), fragment layout
__device__ uint4  g_af[(size_t)2048 * 8192];   // 268 MB

// ---------------- helpers ----------------
__device__ __forceinline__ uint32_t smem_u32(const void* p) {
    uint32_t a;
    asm("{ .reg .u64 t; cvta.to.shared.u64 t, %1; cvt.u32.u64 %0, t; }" : "=r"(a) : "l"(p));
    return a;
}
__device__ __forceinline__ void ldsm4(uint32_t* r, uint32_t addr) {
    asm volatile("ldmatrix.sync.aligned.m8n8.x4.shared.b16 {%0,%1,%2,%3}, [%4];"
        : "=r"(r[0]), "=r"(r[1]), "=r"(r[2]), "=r"(r[3]) : "r"(addr));
}
#define LDS128(r, a) \
    asm volatile("ld.shared.v4.b32 {%0,%1,%2,%3}, [%4];" \
        : "=r"((r)[0]), "=r"((r)[1]), "=r"((r)[2]), "=r"((r)[3]) : "r"(a))
__device__ __forceinline__ void mma16816(float* d, const uint32_t* a, uint32_t b0, uint32_t b1) {
    asm volatile("mma.sync.aligned.m16n8k16.row.col.f32.f16.f16.f32 "
        "{%0,%1,%2,%3}, {%4,%5,%6,%7}, {%8,%9}, {%0,%1,%2,%3};"
        : "+f"(d[0]), "+f"(d[1]), "+f"(d[2]), "+f"(d[3])
        : "r"(a[0]), "r"(a[1]), "r"(a[2]), "r"(a[3]), "r"(b0), "r"(b1));
}
__device__ __forceinline__ void cp16(uint32_t dst, const void* src) {
    asm volatile("cp.async.cg.shared.global [%0], [%1], 16;" :: "r"(dst), "l"(src));
}
#define CP_COMMIT() asm volatile("cp.async.commit_group;" ::: "memory")
#define CP_WAIT1()  asm volatile("cp.async.wait_group 1;" ::: "memory")
#define CP_WAIT0()  asm volatile("cp.async.wait_group 0;" ::: "memory")

__device__ __forceinline__ uint32_t pack2(float v0, float v1) {
    __half2 h = __floats2half2_rn(v0, v1);
    return *(uint32_t*)&h;
}

// ---------------------------------------------------------------------------
// Prologue: z=0: hx = x @ W1x ; z=1: hyb = y @ W1y + b1 ; z=2: W2^T -> fp16
// ---------------------------------------------------------------------------
__global__ void __launch_bounds__(256) prologue_gemm(
    const float* __restrict__ x, const float* __restrict__ y,
    const float* __restrict__ w1x, const float* __restrict__ w1y,
    const float* __restrict__ b1, const float* __restrict__ w2)
{
    int tid = threadIdx.x;

    if (blockIdx.z == 2) {
        int k0 = blockIdx.y * 64, c0 = blockIdx.x * 64;
        #pragma unroll
        for (int s = 0; s < 16; s++) {
            int idx = tid + s * 256;
            int cc = idx >> 6, kk = idx & 63;
            g_w2t[(c0 + cc) * HH + k0 + kk] =
                __float2half_rn(w2[(k0 + kk) * HH + c0 + cc]);
        }
        return;
    }

    const float* A = (blockIdx.z == 0) ? x   : y;
    const float* B = (blockIdx.z == 0) ? w1x : w1y;
    float*       C = (blockIdx.z == 0) ? g_hx : g_hyb;

    int m0 = blockIdx.y * 64, n0 = blockIdx.x * 64;
    __shared__ float sA[16][64 + 2];
    __shared__ float sB[16][64 + 2];
    int ty = tid >> 4, tx = tid & 15;

    float acc[4][4] = {};
    for (int k0 = 0; k0 < XD; k0 += 16) {
        #pragma unroll
        for (int s = 0; s < 4; s++) {
            int idx = tid + s * 256;
            int kk = idx & 15, m = idx >> 4;
            sA[kk][m] = A[(m0 + m) * XD + k0 + kk];
        }
        #pragma unroll
        for (int s = 0; s < 4; s++) {
            int idx = tid + s * 256;
            int nn = idx & 63, kk = idx >> 6;
            sB[kk][nn] = B[(k0 + kk) * HH + n0 + nn];
        }
        __syncthreads();
        #pragma unroll
        for (int kk = 0; kk < 16; kk++) {
            float a[4], b[4];
            #pragma unroll
            for (int u = 0; u < 4; u++) a[u] = sA[kk][ty * 4 + u];
            #pragma unroll
            for (int v = 0; v < 4; v++) b[v] = sB[kk][tx * 4 + v];
            #pragma unroll
            for (int u = 0; u < 4; u++)
                #pragma unroll
                for (int v = 0; v < 4; v++)
                    acc[u][v] = fmaf(a[u], b[v], acc[u][v]);
        }
        __syncthreads();
    }
    #pragma unroll
    for (int u = 0; u < 4; u++)
        #pragma unroll
        for (int v = 0; v < 4; v++) {
            int m = m0 + ty * 4 + u, n = n0 + tx * 4 + v;
            float val = acc[u][v];
            if (blockIdx.z == 1) val += b1[n];
            C[m * HH + n] = val;
        }
}

// ---------------------------------------------------------------------------
// Main HMMA kernel. grid (16, 128), 256 thr, 8 warps (4 m x 2 n), 2 CTAs/SM.
// Phase 1 (nb=0, s=0..15): R8 schedule, builds A frags + stores them (warp_n=0).
// Phase 2 (nb=1..3, s=16..63): A frags replayed via cp.async + LDS.128.
// ---------------------------------------------------------------------------
__global__ void __launch_bounds__(256, 2) main_mma(
    const float* __restrict__ b2, const float* __restrict__ w3,
    const float* __restrict__ b3)
{
    extern __shared__ char smem[];
    uint32_t sb = smem_u32(smem);
    int tid = threadIdx.x, lane = tid & 31, wid = tid >> 5;
    int warp_m = wid >> 1, warp_n = wid & 1;
    int jt = blockIdx.x, it = blockIdx.y;
    const uint32_t afc = (uint32_t)(it * NJT + jt) * 8192u;   // uint4 index base

    float* hx_s  = (float*)(smem + OFF_HX);
    float* hyb_s = (float*)(smem + OFF_HYB);
    float* b2s   = (float*)(smem + OFF_B2);
    float* w3s   = (float*)(smem + OFF_W3);
    float* sRow  = (float*)(smem + OFF_ROW);
    float* sE    = (float*)(smem + OFF_E);

    // ---- group 0: hx (32 rows) + hyb (4 rows) + B stage 0 ----
    #pragma unroll
    for (int u = 0; u < 16; u++) {
        int idx = tid + u * 256;
        int row = idx >> 7, q = idx & 127;
        cp16(sb + OFF_HX + (uint32_t)(row * (HXS*4) + q * 16),
             g_hx + (jt * 32 + row) * HH + q * 4);
    }
    #pragma unroll
    for (int u = 0; u < 2; u++) {
        int idx = tid + u * 256;
        int row = idx >> 7, q = idx & 127;
        cp16(sb + OFF_HYB + (uint32_t)(row * (HXS*4) + q * 16),
             g_hyb + (it * 4 + row) * HH + q * 4);
    }
    #pragma unroll
    for (int u = 0; u < 2; u++) {            // B step 0 (nb=0,kc=0)
        int idx = tid + u * 256;
        int col = idx >> 2, q = idx & 3;
        cp16(sb + OFF_B + (uint32_t)(col * 80 + q * 16),
             g_w2t + col * HH + q * 8);
    }
    CP_COMMIT();
    // ---- group 1: B stage 1 ----
    #pragma unroll
    for (int u = 0; u < 2; u++) {
        int idx = tid + u * 256;
        int col = idx >> 2, q = idx & 3;
        cp16(sb + OFF_B + BSTG + (uint32_t)(col * 80 + q * 16),
             g_w2t + col * HH + 32 + q * 8);
    }
    CP_COMMIT();

    for (int c = tid; c < HH; c += 256) { b2s[c] = b2[c]; w3s[c] = w3[c]; }

    const int g  = lane >> 2;          // 0..7
    const int qk = (lane & 3) * 2;     // 0,2,4,6
    const float* hyr = hyb_s + warp_m * HXS;

    float ptl[4] = {0.f, 0.f, 0.f, 0.f};
    float acc[2][8][4];
    uint32_t ah_cur[2][4], ah_nxt[2][4];

    const uint32_t bcol = (uint32_t)(warp_n * 64 + (lane & 7) + ((lane >> 4) & 1) * 8);
    const uint32_t bchk_base = (uint32_t)((lane >> 3) & 1);

    #define BUILD_A(dst, kb_) do {                                              \
        int kb = (kb_);                                                         \
        _Pragma("unroll")                                                       \
        for (int tm = 0; tm < 2; tm++) {                                        \
            int r0 = (warp_m * 32 + tm * 16 + g) & 31;                          \
            int r1 = (warp_m * 32 + tm * 16 + 8 + g) & 31;                      \
            float2 x00 = *(const float2*)(hx_s + r0 * HXS + kb + qk);           \
            float2 x01 = *(const float2*)(hx_s + r0 * HXS + kb + qk + 8);       \
            float2 x10 = *(const float2*)(hx_s + r1 * HXS + kb + qk);           \
            float2 x11 = *(const float2*)(hx_s + r1 * HXS + kb + qk + 8);       \
            float2 y0  = *(const float2*)(hyr + kb + qk);                       \
            float2 y1  = *(const float2*)(hyr + kb + qk + 8);                   \
            dst[tm][0] = pack2(fmaxf(x00.x + y0.x, 0.f), fmaxf(x00.y + y0.y, 0.f)); \
            dst[tm][1] = pack2(fmaxf(x10.x + y0.x, 0.f), fmaxf(x10.y + y0.y, 0.f)); \
            dst[tm][2] = pack2(fmaxf(x01.x + y1.x, 0.f), fmaxf(x01.y + y1.y, 0.f)); \
            dst[tm][3] = pack2(fmaxf(x11.x + y1.x, 0.f), fmaxf(x11.y + y1.y, 0.f)); \
        }                                                                       \
    } while (0)

    #define MMA_BLOCK(ah, stage, ks) do {                                       \
        uint32_t bchk = (uint32_t)((ks) * 2) + bchk_base;                       \
        _Pragma("unroll")                                                       \
        for (int p = 0; p < 4; p++) {                                           \
            uint32_t addr = (stage) + (bcol + p * 16) * 80 + bchk * 16;         \
            uint32_t bh[4];                                                     \
            ldsm4(bh, addr);                                                    \
            _Pragma("unroll")                                                   \
            for (int tm = 0; tm < 2; tm++) {                                    \
                mma16816(acc[tm][2*p],   ah[tm], bh[0], bh[1]);                 \
                mma16816(acc[tm][2*p+1], ah[tm], bh[2], bh[3]);                 \
            }                                                                   \
        }                                                                       \
    } while (0)

    #define STG_FRAG(ah, kc_, ks_) do {                                        \
        _Pragma("unroll")                                                      \
        for (int tm = 0; tm < 2; tm++) {                                       \
            uint4 v; v.x = ah[tm][0]; v.y = ah[tm][1];                         \
            v.z = ah[tm][2]; v.w = ah[tm][3];                                  \
            __stcg(&g_af[afc + (uint32_t)((kc_) * 512 +                        \
                   (((ks_) * 4 + warp_m) * 2 + tm) * 32 + lane)], v);          \
        }                                                                      \
    } while (0)

    #define FOLD(nb_) do {                                                     \
        _Pragma("unroll")                                                      \
        for (int tm = 0; tm < 2; tm++)                                         \
            _Pragma("unroll")                                                  \
            for (int tn = 0; tn < 8; tn++) {                                   \
                int c0 = (nb_) * 128 + warp_n * 64 + tn * 8 + (lane & 3) * 2;  \
                float w3a = w3s[c0], w3b = w3s[c0 + 1];                        \
                float b2a = b2s[c0], b2b = b2s[c0 + 1];                        \
                float v0 = acc[tm][tn][0] + b2a;                               \
                float v1 = acc[tm][tn][1] + b2b;                               \
                float v2 = acc[tm][tn][2] + b2a;                               \
                float v3 = acc[tm][tn][3] + b2b;                               \
                ptl[tm*2+0] = fmaf(fmaxf(v0, 0.f), w3a, fmaf(fmaxf(v1, 0.f), w3b, ptl[tm*2+0])); \
                ptl[tm*2+1] = fmaf(fmaxf(v2, 0.f), w3a, fmaf(fmaxf(v3, 0.f), w3b, ptl[tm*2+1])); \
            }                                                                  \
    } while (0)

    // wait for group 0 (hx/hyb/stage0); group 1 may stay in flight
    CP_WAIT1();
    __syncthreads();

    BUILD_A(ah_cur, 0);   // (s=0, ks=0)

    // ================= PHASE 1: nb = 0, s = 0..15 =================
    for (int s = 0; s < 16; s++) {
        int kc = s;

        if (s) { CP_WAIT1(); __syncthreads(); }

        // prefetch B for step s+2 into ring slot (s+2)%3
        {
            int s2 = s + 2;
            int nb2 = s2 >> 4, kc2 = s2 & 15;
            uint32_t stg = sb + OFF_B + (uint32_t)((s2 % 3) * BSTG);
            #pragma unroll
            for (int u = 0; u < 2; u++) {
                int idx = tid + u * 256;
                int col = idx >> 2, q = idx & 3;
                cp16(stg + (uint32_t)(col * 80 + q * 16),
                     g_w2t + (nb2 * 128 + col) * HH + kc2 * 32 + q * 8);
            }
            CP_COMMIT();
        }

        if (kc == 0) {
            #pragma unroll
            for (int tm = 0; tm < 2; tm++)
                #pragma unroll
                for (int tn = 0; tn < 8; tn++)
                    #pragma unroll
                    for (int v = 0; v < 4; v++) acc[tm][tn][v] = 0.f;
        }

        uint32_t stage = sb + OFF_B + (uint32_t)((s % 3) * BSTG);

        BUILD_A(ah_nxt, kc * 32 + 16);
        if (warp_n == 0) STG_FRAG(ah_cur, kc, 0);
        MMA_BLOCK(ah_cur, stage, 0);
        BUILD_A(ah_cur, ((s + 1) & 15) * 32);
        if (warp_n == 0) STG_FRAG(ah_nxt, kc, 1);
        MMA_BLOCK(ah_nxt, stage, 1);

        if (kc == 15) FOLD(0);
    }

    // ================= boundary: start A replay ring =================
    __syncthreads();      // all warps finished reading hx (phase 1 done)
    {
        // A(16)->slot 1 (kc=0), A(17)->slot 2 (kc=1); one commit group
        #pragma unroll
        for (int u = 0; u < 2; u++) {
            int chunk = tid + u * 256;
            cp16(sb + (uint32_t)(1 * 8192 + chunk * 16),
                 &g_af[afc + (uint32_t)(0 * 512 + chunk)]);
        }
        #pragma unroll
        for (int u = 0; u < 2; u++) {
            int chunk = tid + u * 256;
            cp16(sb + (uint32_t)(2 * 8192 + chunk * 16),
                 &g_af[afc + (uint32_t)(1 * 512 + chunk)]);
        }
        CP_COMMIT();
    }
    CP_WAIT0();
    __syncthreads();

    // ================= PHASE 2: nb = 1..3, s = 16..63 =================
    for (int s = 16; s < 64; s++) {
        int nb = s >> 4, kc = s & 15;

        if (s > 16) {
            if (s < 63) { CP_WAIT1(); } else { CP_WAIT0(); }
            __syncthreads();
        }

        // prefetch B + A for step s+2 (one group)
        if (s < 62) {
            int s2 = s + 2;
            int nb2 = s2 >> 4, kc2 = s2 & 15;
            int slot2 = s2 % 3;
            uint32_t stg = sb + OFF_B + (uint32_t)(slot2 * BSTG);
            #pragma unroll
            for (int u = 0; u < 2; u++) {
                int idx = tid + u * 256;
                int col = idx >> 2, q = idx & 3;
                cp16(stg + (uint32_t)(col * 80 + q * 16),
                     g_w2t + (nb2 * 128 + col) * HH + kc2 * 32 + q * 8);
            }
            #pragma unroll
            for (int u = 0; u < 2; u++) {
                int chunk = tid + u * 256;
                cp16(sb + (uint32_t)(slot2 * 8192 + chunk * 16),
                     &g_af[afc + (uint32_t)(kc2 * 512 + chunk)]);
            }
            CP_COMMIT();
        }

        if (kc == 0) {
            #pragma unroll
            for (int tm = 0; tm < 2; tm++)
                #pragma unroll
                for (int tn = 0; tn < 8; tn++)
                    #pragma unroll
                    for (int v = 0; v < 4; v++) acc[tm][tn][v] = 0.f;
        }

        uint32_t bstage = sb + OFF_B + (uint32_t)((s % 3) * BSTG);
        uint32_t aslot  = sb + (uint32_t)((s % 3) * 8192);

        #pragma unroll
        for (int ks = 0; ks < 2; ks++) {
            uint32_t af[2][4];
            #pragma unroll
            for (int tm = 0; tm < 2; tm++)
                LDS128(af[tm], aslot +
                    (uint32_t)((((ks * 4 + warp_m) * 2 + tm) * 32 + lane) * 16));
            MMA_BLOCK(af, bstage, ks);
        }

        if (kc == 15) FOLD(nb);
    }

    // ---- reduce across the 4 column-thread groups (same rows) ----
    #pragma unroll
    for (int u = 0; u < 4; u++) {
        ptl[u] += __shfl_xor_sync(0xffffffffu, ptl[u], 1);
        ptl[u] += __shfl_xor_sync(0xffffffffu, ptl[u], 2);
    }
    __syncthreads();
    if ((lane & 3) == 0) {
        int q = lane >> 2;
        sRow[(warp_m * 32 +  0 + q) * 2 + warp_n] = ptl[0];
        sRow[(warp_m * 32 +  8 + q) * 2 + warp_n] = ptl[1];
        sRow[(warp_m * 32 + 16 + q) * 2 + warp_n] = ptl[2];
        sRow[(warp_m * 32 + 24 + q) * 2 + warp_n] = ptl[3];
    }
    __syncthreads();

    if (tid < 128) {
        float ssum = sRow[tid * 2] + sRow[tid * 2 + 1] + b3[0];
        float T1 = (ssum > 20.f) ? ssum : log1pf(expf(ssum));
        int ii = it * 4 + (tid >> 5);
        int jj = jt * 32 + (tid & 31);
        if (ii == jj) g_t0[ii] = T1;
        sE[tid] = expf(T1);
    }
    __syncthreads();

    if (tid < 4) {
        float ssum = 0.f;
        #pragma unroll
        for (int jl = 0; jl < 32; jl++) ssum += sE[tid * 32 + jl];
        g_partial[(it * 4 + tid) * NJT + jt] = ssum;
    }
}

// ---------------------------------------------------------------------------
// Finalize
// ---------------------------------------------------------------------------
__global__ void finalize_kernel(float* __restrict__ out)
{
    int tid = threadIdx.x;
    float s = 0.f;
    #pragma unroll
    for (int jt = 0; jt < NJT; jt++) s += g_partial[tid * NJT + jt];
    float val = g_t0[tid] - logf(s);

    __shared__ float sh[512];
    sh[tid] = val;
    __syncthreads();
    for (int off = 256; off > 0; off >>= 1) {
        if (tid < off) sh[tid] += sh[tid + off];
        __syncthreads();
    }
    if (tid == 0) out[0] = sh[0] / 512.f + logf(512.f);
}

extern "C" void kernel_launch(void* const* d_in, const int* in_sizes, int n_in,
                              void* d_out, int out_size)
{
    const float* x   = (const float*)d_in[0];
    const float* y   = (const float*)d_in[1];
    const float* w1x = (const float*)d_in[2];
    const float* w1y = (const float*)d_in[3];
    const float* b1  = (const float*)d_in[4];
    const float* w2  = (const float*)d_in[5];
    const float* b2  = (const float*)d_in[6];
    const float* w3  = (const float*)d_in[7];
    const float* b3  = (const float*)d_in[8];
    float* out = (float*)d_out;

    cudaFuncSetAttribute(main_mma, cudaFuncAttributeMaxDynamicSharedMemorySize, SMEM_MAIN);

    dim3 g1(8, 8, 3);
    prologue_gemm<<<g1, 256>>>(x, y, w1x, w1y, b1, w2);
    dim3 g2(NJT, NIT);
    main_mma<<<g2, 256, SMEM_MAIN>>>(b2, w3, b3);
    finalize_kernel<<<1, 512>>>(out);
}